// round 17
// baseline (speedup 1.0000x reference)
#include <cuda_runtime.h>

#define Bn     16
#define Nn     9216
#define Cn     256
#define Kn     21
#define ITERS  20
#define PANELS 36        /* 256-point panels; one panel per assign block */

// ---------------- device scratch (no allocations allowed) ----------------
__device__ float g_xT[(size_t)Bn * Cn * Nn];               // x transposed [b][c][n]
__device__ float g_xsq[(size_t)Bn * Nn];                   // ||x_n||^2, seq unfused asc-c
__device__ float g_cent[Bn * Kn * Cn];                     // centroids [b][k][c]
__device__ float g_csq[Bn * Kn];                           // ||c_k||^2, seq unfused asc-c
__device__ float g_psums[(size_t)PANELS * Bn * Kn * Cn];   // per-panel partial sums
__device__ int   g_pcnt[PANELS * Bn * Kn];                 // per-panel partial counts
__device__ int   g_i64;                                    // 1 if init_idx is int64

// ---------------- dtype detector for init_idx (int64 vs int32) ----------------
__global__ void detect_kernel(const unsigned long long* __restrict__ idx) {
    if (threadIdx.x == 0 && blockIdx.x == 0) {
        int f = 1;
        // Read exactly 1344 bytes = sizeof(init_idx) under either dtype.
        for (int i = 0; i < (Bn * Kn) / 2; i++)
            if (idx[i] >= (unsigned long long)Nn) f = 0;
        g_i64 = f;
    }
}

// ---------------- x_sq: 1 thread per point, seq unfused ascending-c ----------------
__global__ void xsq_kernel(const float* __restrict__ x) {
    long long P = (long long)blockIdx.x * 256 + threadIdx.x;   // over Bn*Nn
    const float4* row4 = (const float4*)(x + (size_t)P * Cn);
    float s = 0.f;
#pragma unroll 8
    for (int i = 0; i < Cn / 4; i++) {
        float4 v = row4[i];
        s = __fadd_rn(s, __fmul_rn(v.x, v.x));
        s = __fadd_rn(s, __fmul_rn(v.y, v.y));
        s = __fadd_rn(s, __fmul_rn(v.z, v.z));
        s = __fadd_rn(s, __fmul_rn(v.w, v.w));
    }
    g_xsq[P] = s;
}

// ---------------- transpose x[b][n][c] -> g_xT[b][c][n] (exact copy) ----------------
__global__ void transpose_kernel(const float* __restrict__ x) {
    __shared__ float t[32][33];
    int b  = blockIdx.z;
    int n0 = blockIdx.x * 32, c0 = blockIdx.y * 32;
    int tx = threadIdx.x, ty = threadIdx.y;
#pragma unroll
    for (int r = 0; r < 4; r++)
        t[ty + 8 * r][tx] = x[(size_t)(b * Nn + n0 + ty + 8 * r) * Cn + c0 + tx];
    __syncthreads();
#pragma unroll
    for (int r = 0; r < 4; r++)
        g_xT[(size_t)(b * Cn + c0 + ty + 8 * r) * Nn + n0 + tx] = t[tx][ty + 8 * r];
}

// ---------------- initial centroids: gather + sequential unfused ||c||^2 ----------------
__global__ void init_kernel(const float* __restrict__ x, const void* __restrict__ idxp) {
    __shared__ float sv[Cn];
    int bk = blockIdx.x;              // b*Kn + k
    int b  = bk / Kn;
    int tid = threadIdx.x;
    long long n;
    if (g_i64) n = ((const long long*)idxp)[bk];
    else       n = (long long)((const int*)idxp)[bk];
    float v = x[(size_t)(b * Nn + (int)n) * Cn + tid];
    g_cent[bk * Cn + tid] = v;
    sv[tid] = v;
    __syncthreads();
    if (tid == 0) {
        float s = 0.f;                 // square-then-add, strictly ascending c
        for (int c = 0; c < Cn; c++)
            s = __fadd_rn(s, __fmul_rn(sv[c], sv[c]));
        g_csq[bk] = s;
    }
}

// ---------------- fused assignment + per-panel scatter-sum ----------------
// One 256-point panel per block, one point per thread, 4 CTAs/SM.
// Both phases read ONLY g_xT: phase 2 re-reads the block's 256KB slice,
// which phase 1 just pulled through L2 -> phase-2 DRAM traffic ~0.
__global__ __launch_bounds__(256, 4) void assign_kernel() {
    __shared__ float         sc[Cn][24];     // centroids channel-major (21 used, pad 24)
    __shared__ float         ssum[Kn][Cn];   // per-panel partial sums
    __shared__ float         scsq[Kn];
    __shared__ int           scnt[Kn];
    __shared__ unsigned char sasg[256];

    int b = blockIdx.y, p = blockIdx.x, tid = threadIdx.x;

    // Stage centroids transposed: sc[c][k] = cent[k][c]
#pragma unroll
    for (int k = 0; k < Kn; k++) sc[tid][k] = g_cent[(b * Kn + k) * Cn + tid];
    sc[tid][21] = 0.f; sc[tid][22] = 0.f; sc[tid][23] = 0.f;
    if (tid < Kn) { scsq[tid] = g_csq[b * Kn + tid]; scnt[tid] = 0; }
#pragma unroll
    for (int k = 0; k < Kn; k++) ssum[k][tid] = 0.f;
    __syncthreads();

    // ---- phase 1: dot for ONE point, ascending-c FFMA chain ----
    int n = p * 256 + tid;
    const float* xTb = g_xT + (size_t)b * Cn * Nn;
    float xsq = g_xsq[(size_t)b * Nn + n];

    float4 a[5];                       // k = 0..19
    float  a20 = 0.f;                  // k = 20
#pragma unroll
    for (int q = 0; q < 5; q++) a[q] = make_float4(0.f, 0.f, 0.f, 0.f);

#pragma unroll 2
    for (int c = 0; c < Cn; c++) {
        float xv = xTb[(size_t)c * Nn + n];          // coalesced 128B per warp
        const float4* cw4 = (const float4*)&sc[c][0];
#pragma unroll
        for (int q = 0; q < 5; q++) {
            float4 cw = cw4[q];                       // broadcast LDS.128
            a[q].x = __fmaf_rn(xv, cw.x, a[q].x);
            a[q].y = __fmaf_rn(xv, cw.y, a[q].y);
            a[q].z = __fmaf_rn(xv, cw.z, a[q].z);
            a[q].w = __fmaf_rn(xv, cw.w, a[q].w);
        }
        a20 = __fmaf_rn(xv, sc[c][20], a20);
    }

    // ---- argmin over d = fl(fl(x_sq - 2*dot) + csq), ascending k, first-min ----
    {
        const float* ap = (const float*)a;            // k = 0..19 contiguous
        float best = __fadd_rn(__fadd_rn(xsq, -__fmul_rn(2.f, ap[0])), scsq[0]);
        int   bi = 0;
#pragma unroll
        for (int k = 1; k < 20; k++) {
            float d = __fadd_rn(__fadd_rn(xsq, -__fmul_rn(2.f, ap[k])), scsq[k]);
            if (d < best) { best = d; bi = k; }
        }
        {
            float d = __fadd_rn(__fadd_rn(xsq, -__fmul_rn(2.f, a20)), scsq[20]);
            if (d < best) { best = d; bi = 20; }
        }
        sasg[tid] = (unsigned char)bi;
        atomicAdd(&scnt[bi], 1);
    }
    __syncthreads();

    // ---- phase 2: one 256-point panel, strictly sequential ascending n ----
    // thread = channel; reads its xT row (1KB contiguous per thread, L2-hot
    // from phase 1; each 128B line consumed by one thread via L1).
    // Values are bitwise identical to x[n][c]; add order unchanged.
    const float* xTrow = g_xT + ((size_t)b * Cn + tid) * Nn + p * 256;
    int aprev = sasg[0];
    float racc = 0.f;                  // ssum rows start at 0
    for (int q = 0; q < 256; q += 8) {
        float4 u0 = *(const float4*)(xTrow + q);      // LDG.128
        float4 u1 = *(const float4*)(xTrow + q + 4);  // LDG.128
        float v[8] = {u0.x, u0.y, u0.z, u0.w, u1.x, u1.y, u1.z, u1.w};
#pragma unroll
        for (int j = 0; j < 8; j++) {
            int a2 = sasg[q + j];
            if (a2 != aprev) {
                ssum[aprev][tid] = racc;
                racc = ssum[a2][tid];
                aprev = a2;
            }
            racc = __fadd_rn(racc, v[j]);
        }
    }
    ssum[aprev][tid] = racc;
    __syncthreads();

    // ---- deterministic panel writeback (plain stores, no global atomics) ----
    size_t base = (size_t)((p * Bn + b) * Kn) * Cn;
#pragma unroll
    for (int k = 0; k < Kn; k++) g_psums[base + k * Cn + tid] = ssum[k][tid];
    if (tid < Kn) g_pcnt[(p * Bn + b) * Kn + tid] = scnt[tid];
}

// ---------------- centroid update + sequential unfused ||c||^2 ----------------
__global__ void update_kernel(float* __restrict__ out) {
    __shared__ float scn[Cn];
    int bk = blockIdx.x;
    int tid = threadIdx.x;
    float s = 0.f;
    int cnt = 0;
#pragma unroll
    for (int t = 0; t < PANELS; t++) {         // 36 panels, ascending n
        s = __fadd_rn(s, g_psums[(size_t)(t * Bn * Kn + bk) * Cn + tid]);
        cnt += g_pcnt[t * Bn * Kn + bk];
    }
    float oldc = g_cent[bk * Cn + tid];
    float cn = (cnt > 0) ? __fdiv_rn(s, (float)cnt) : oldc;   // exact rn divide
    g_cent[bk * Cn + tid] = cn;
    if (out) out[bk * Cn + tid] = cn;
    scn[tid] = cn;
    __syncthreads();
    if (tid == 0) {
        float q = 0.f;                 // square-then-add, strictly ascending c
        for (int c = 0; c < Cn; c++)
            q = __fadd_rn(q, __fmul_rn(scn[c], scn[c]));
        g_csq[bk] = q;
    }
}

// ---------------- launch ----------------
extern "C" void kernel_launch(void* const* d_in, const int* in_sizes, int n_in,
                              void* d_out, int out_size) {
    const float* x   = (const float*)d_in[0];
    const void*  idx = d_in[1];

    detect_kernel<<<1, 32>>>((const unsigned long long*)idx);
    init_kernel<<<Bn * Kn, 256>>>(x, idx);
    xsq_kernel<<<(Bn * Nn) / 256, 256>>>(x);
    transpose_kernel<<<dim3(Nn / 32, Cn / 32, Bn), dim3(32, 8)>>>(x);

    for (int it = 0; it < ITERS; ++it) {
        assign_kernel<<<dim3(PANELS, Bn), 256>>>();
        update_kernel<<<Bn * Kn, 256>>>(it == ITERS - 1 ? (float*)d_out : nullptr);
    }
}